// round 1
// baseline (speedup 1.0000x reference)
#include <cuda_runtime.h>
#include <math.h>

// Problem constants (static per reference)
#define NBATCH 8
#define LQ     5440
#define TTOK   (NBATCH*LQ)      // 43520
#define DIM    256
#define NHEAD  8
#define HD     32
#define NLVL   4
#define NPT    4
#define DFF    1024

// Scratch (device globals; no runtime allocation)
__device__ float g_value[(size_t)TTOK*DIM];
__device__ float g_off  [(size_t)TTOK*DIM];
__device__ float g_attn [(size_t)TTOK*128];
__device__ float g_samp [(size_t)TTOK*DIM];
__device__ float g_src2 [(size_t)TTOK*DIM];
__device__ float g_x    [(size_t)TTOK*DIM];
__device__ float g_hid  [(size_t)TTOK*DFF];
__device__ float g_ffn  [(size_t)TTOK*DIM];

// ---------------------------------------------------------------------------
// Tiled fp32 GEMM: C[M x Nc] = act( (A (+A2)) @ W + bias )
// Block computes 64x64 tile; 16x16 threads, 4x4 per thread.
// M = TTOK (multiple of 64), Nc in {128,256,1024}, K in {256,1024}.
// ---------------------------------------------------------------------------
template<int ACT, int HASA2>
__global__ void gemm_kernel(const float* __restrict__ A, const float* __restrict__ A2,
                            const float* __restrict__ W, const float* __restrict__ bias,
                            float* __restrict__ C, int K, int Nc)
{
    __shared__ float As[16][68];   // [k][row], padded: row stride 272B (16B aligned)
    __shared__ float Wsh[16][68];  // [k][col]

    const int tx = threadIdx.x, ty = threadIdx.y;
    const int tid = ty * 16 + tx;
    const int row0 = blockIdx.y * 64;
    const int col0 = blockIdx.x * 64;

    float acc[4][4];
#pragma unroll
    for (int i = 0; i < 4; i++)
#pragma unroll
        for (int j = 0; j < 4; j++) acc[i][j] = 0.f;

    for (int k0 = 0; k0 < K; k0 += 16) {
#pragma unroll
        for (int i = 0; i < 4; i++) {
            int idx = tid + i * 256;          // 0..1023
            int r  = idx >> 4, kk = idx & 15; // A tile: 64 rows x 16 k
            size_t ga = (size_t)(row0 + r) * K + (k0 + kk);
            float a = A[ga];
            if (HASA2) a += A2[ga];
            As[kk][r] = a;
            int kw = idx >> 6, c = idx & 63;  // W tile: 16 k x 64 cols
            Wsh[kw][c] = W[(size_t)(k0 + kw) * Nc + (col0 + c)];
        }
        __syncthreads();
#pragma unroll
        for (int kk = 0; kk < 16; kk++) {
            float4 av = *(const float4*)(&As[kk][ty * 4]);
            float4 wv = *(const float4*)(&Wsh[kk][tx * 4]);
            float a[4] = {av.x, av.y, av.z, av.w};
            float w[4] = {wv.x, wv.y, wv.z, wv.w};
#pragma unroll
            for (int i = 0; i < 4; i++)
#pragma unroll
                for (int j = 0; j < 4; j++) acc[i][j] = fmaf(a[i], w[j], acc[i][j]);
        }
        __syncthreads();
    }

#pragma unroll
    for (int i = 0; i < 4; i++) {
        int r = row0 + ty * 4 + i;
        int c = col0 + tx * 4;
        float4 o;
        o.x = acc[i][0] + bias[c + 0];
        o.y = acc[i][1] + bias[c + 1];
        o.z = acc[i][2] + bias[c + 2];
        o.w = acc[i][3] + bias[c + 3];
        if (ACT) {
            o.x = fmaxf(o.x, 0.f); o.y = fmaxf(o.y, 0.f);
            o.z = fmaxf(o.z, 0.f); o.w = fmaxf(o.w, 0.f);
        }
        *(float4*)(&C[(size_t)r * Nc + c]) = o;
    }
}

// ---------------------------------------------------------------------------
// Deformable sampling with fused softmax.
// Grid: TTOK blocks; 256 threads = 8 heads x 32 dims.
// out[t, h*32+d] = sum_{l,p} softmax(attn)[l,p] * bilinear(value_l, loc)[d]
// ---------------------------------------------------------------------------
__global__ void sample_kernel(const float* __restrict__ value,
                              const float* __restrict__ offs,
                              const float* __restrict__ logits,
                              const float* __restrict__ ref,
                              float* __restrict__ out)
{
    const int t = blockIdx.x;          // n*LQ + q
    const int n = t / LQ;
    const int h = threadIdx.x >> 5;
    const int d = threadIdx.x & 31;

    // Softmax over the 16 (level,point) logits for this (token, head).
    float lg[16];
    const float* lp = logits + (size_t)t * 128 + h * 16;
    float mx = -1e30f;
#pragma unroll
    for (int j = 0; j < 16; j++) { lg[j] = lp[j]; mx = fmaxf(mx, lg[j]); }
    float ssum = 0.f;
#pragma unroll
    for (int j = 0; j < 16; j++) { lg[j] = expf(lg[j] - mx); ssum += lg[j]; }
    const float inv = 1.f / ssum;

    const float* op = offs + (size_t)t * DIM + h * (NLVL * NPT * 2);
    const int Hs[4] = {64, 32, 16, 8};
    const int St[4] = {0, 4096, 5120, 5376};

    float acc = 0.f;
#pragma unroll
    for (int l = 0; l < NLVL; l++) {
        const int H = Hs[l];
        const int W = Hs[l];            // square levels
        const float fH = (float)H, fW = (float)W;
        const float invW = 1.f / fW, invH = 1.f / fH;
        const float refx = ref[((size_t)t * NLVL + l) * 2 + 0];
        const float refy = ref[((size_t)t * NLVL + l) * 2 + 1];
        const float* vbase = value + ((size_t)(n * LQ + St[l])) * DIM + h * HD + d;
#pragma unroll
        for (int p = 0; p < NPT; p++) {
            float ox = op[(l * NPT + p) * 2 + 0];
            float oy = op[(l * NPT + p) * 2 + 1];
            float xf = (refx + ox * invW) * fW - 0.5f;
            float yf = (refy + oy * invH) * fH - 0.5f;
            float x0f = floorf(xf), y0f = floorf(yf);
            int x0 = (int)x0f, y0 = (int)y0f;
            float wx1 = xf - x0f, wy1 = yf - y0f;
            float wx0 = 1.f - wx1, wy0 = 1.f - wy1;

            float v00 = 0.f, v01 = 0.f, v10 = 0.f, v11 = 0.f;
            bool xin0 = (x0 >= 0) & (x0 < W);
            bool xin1 = (x0 + 1 >= 0) & (x0 + 1 < W);
            bool yin0 = (y0 >= 0) & (y0 < H);
            bool yin1 = (y0 + 1 >= 0) & (y0 + 1 < H);
            if (yin0 && xin0) v00 = vbase[(size_t)(y0 * W + x0) * DIM];
            if (yin0 && xin1) v01 = vbase[(size_t)(y0 * W + x0 + 1) * DIM];
            if (yin1 && xin0) v10 = vbase[(size_t)((y0 + 1) * W + x0) * DIM];
            if (yin1 && xin1) v11 = vbase[(size_t)((y0 + 1) * W + x0 + 1) * DIM];

            float bil = (v00 * wx0 + v01 * wx1) * wy0 + (v10 * wx0 + v11 * wx1) * wy1;
            acc = fmaf(lg[l * NPT + p] * inv, bil, acc);
        }
    }
    out[(size_t)t * DIM + threadIdx.x] = acc;
}

// ---------------------------------------------------------------------------
// LayerNorm over 256: out = LN(a + b) * g + beta. One warp per token.
// ---------------------------------------------------------------------------
__global__ void ln_kernel(const float* __restrict__ a, const float* __restrict__ b,
                          const float* __restrict__ g, const float* __restrict__ beta,
                          float* __restrict__ out)
{
    const int t = blockIdx.x * 4 + (threadIdx.x >> 5);
    const int lane = threadIdx.x & 31;
    const float* pa = a + (size_t)t * DIM;
    const float* pb = b + (size_t)t * DIM;

    float v[8];
    float s = 0.f;
#pragma unroll
    for (int i = 0; i < 8; i++) {
        int c = lane + i * 32;
        v[i] = pa[c] + pb[c];
        s += v[i];
    }
#pragma unroll
    for (int o = 16; o; o >>= 1) s += __shfl_xor_sync(0xffffffffu, s, o);
    const float mean = s * (1.f / 256.f);
    float var = 0.f;
#pragma unroll
    for (int i = 0; i < 8; i++) { float dd = v[i] - mean; var += dd * dd; }
#pragma unroll
    for (int o = 16; o; o >>= 1) var += __shfl_xor_sync(0xffffffffu, var, o);
    const float rstd = rsqrtf(var * (1.f / 256.f) + 1e-5f);
#pragma unroll
    for (int i = 0; i < 8; i++) {
        int c = lane + i * 32;
        out[(size_t)t * DIM + c] = (v[i] - mean) * rstd * g[c] + beta[c];
    }
}

// ---------------------------------------------------------------------------
extern "C" void kernel_launch(void* const* d_in, const int* in_sizes, int n_in,
                              void* d_out, int out_size)
{
    const float* src  = (const float*)d_in[0];
    const float* pos  = (const float*)d_in[1];
    const float* refp = (const float*)d_in[2];
    // d_in[3] = spatial_shapes (int32), static — unused
    const float* Wv   = (const float*)d_in[4];
    const float* bv   = (const float*)d_in[5];
    const float* Wo   = (const float*)d_in[6];
    const float* bo   = (const float*)d_in[7];
    const float* Wa   = (const float*)d_in[8];
    const float* ba   = (const float*)d_in[9];
    const float* Wout = (const float*)d_in[10];
    const float* bout = (const float*)d_in[11];
    const float* g1   = (const float*)d_in[12];
    const float* be1  = (const float*)d_in[13];
    const float* W1   = (const float*)d_in[14];
    const float* b1   = (const float*)d_in[15];
    const float* W2   = (const float*)d_in[16];
    const float* b2   = (const float*)d_in[17];
    const float* g2   = (const float*)d_in[18];
    const float* be2  = (const float*)d_in[19];
    float* out = (float*)d_out;

    float *pv, *poff, *pattn, *psamp, *psrc2, *px, *phid, *pffn;
    cudaGetSymbolAddress((void**)&pv,    g_value);
    cudaGetSymbolAddress((void**)&poff,  g_off);
    cudaGetSymbolAddress((void**)&pattn, g_attn);
    cudaGetSymbolAddress((void**)&psamp, g_samp);
    cudaGetSymbolAddress((void**)&psrc2, g_src2);
    cudaGetSymbolAddress((void**)&px,    g_x);
    cudaGetSymbolAddress((void**)&phid,  g_hid);
    cudaGetSymbolAddress((void**)&pffn,  g_ffn);

    dim3 tb(16, 16);
    const int MT = TTOK / 64;   // 680 row tiles

    // value = src @ Wv + bv
    gemm_kernel<0, 0><<<dim3(DIM / 64, MT), tb>>>(src, nullptr, Wv, bv, pv, DIM, DIM);
    // offsets = (src+pos) @ Woff + boff
    gemm_kernel<0, 1><<<dim3(DIM / 64, MT), tb>>>(src, pos, Wo, bo, poff, DIM, DIM);
    // attn logits = (src+pos) @ Wattn + battn
    gemm_kernel<0, 1><<<dim3(128 / 64, MT), tb>>>(src, pos, Wa, ba, pattn, DIM, 128);
    // deformable sampling (softmax fused)
    sample_kernel<<<TTOK, 256>>>(pv, poff, pattn, refp, psamp);
    // src2 = samp @ Wout + bout
    gemm_kernel<0, 0><<<dim3(DIM / 64, MT), tb>>>(psamp, nullptr, Wout, bout, psrc2, DIM, DIM);
    // x = LN1(src + src2)
    ln_kernel<<<TTOK / 4, 128>>>(src, psrc2, g1, be1, px);
    // hid = relu(x @ W1 + b1)
    gemm_kernel<1, 0><<<dim3(DFF / 64, MT), tb>>>(px, nullptr, W1, b1, phid, DIM, DFF);
    // ffn = hid @ W2 + b2
    gemm_kernel<0, 0><<<dim3(DIM / 64, MT), tb>>>(phid, nullptr, W2, b2, pffn, DFF, DIM);
    // out = LN2(x + ffn)
    ln_kernel<<<TTOK / 4, 128>>>(px, pffn, g2, be2, out);
}

// round 3
// speedup vs baseline: 1.9612x; 1.9612x over previous
#include <cuda_runtime.h>
#include <cstdint>
#include <math.h>

// Problem constants (static per reference)
#define NBATCH 8
#define LQ     5440
#define TTOK   (NBATCH*LQ)      // 43520
#define DIM    256
#define NHEAD  8
#define HD     32
#define NLVL   4
#define NPT    4
#define DFF    1024

// Scratch (device globals; no runtime allocation)
__device__ float g_value[(size_t)TTOK*DIM];
__device__ float g_off  [(size_t)TTOK*DIM];
__device__ float g_attn [(size_t)TTOK*128];
__device__ float g_samp [(size_t)TTOK*DIM];
__device__ float g_src2 [(size_t)TTOK*DIM];
__device__ float g_x    [(size_t)TTOK*DIM];
__device__ float g_hid  [(size_t)TTOK*DFF];
__device__ float g_ffn  [(size_t)TTOK*DIM];
// Transposed (N-major -> [N][K]) tf32-rounded weights
__device__ float g_wtv  [256*256];
__device__ float g_wtoff[256*256];
__device__ float g_wtattn[128*256];
__device__ float g_wtout[256*256];
__device__ float g_wt1  [1024*256];
__device__ float g_wt2  [256*1024];

// ---------------------------------------------------------------------------
// Weight transpose + tf32 round: Wt[n*K + k] = rna_tf32(W[k*N + n])
// ---------------------------------------------------------------------------
__global__ void transpose_tf32(const float* __restrict__ W, float* __restrict__ Wt,
                               int K, int N) {
    int idx = blockIdx.x * 256 + threadIdx.x;
    if (idx < K * N) {
        int n = idx / K, k = idx - n * K;
        float v = W[(size_t)k * N + n];
        uint32_t t;
        asm("cvt.rna.tf32.f32 %0, %1;" : "=r"(t) : "f"(v));
        ((uint32_t*)Wt)[idx] = t;
    }
}

// ---------------------------------------------------------------------------
// mma.sync tf32 16x8x8
// ---------------------------------------------------------------------------
__device__ __forceinline__ void mma_tf32(float* c, uint32_t a0, uint32_t a1,
                                         uint32_t a2, uint32_t a3,
                                         uint32_t b0, uint32_t b1) {
    asm volatile(
        "mma.sync.aligned.m16n8k8.row.col.f32.tf32.tf32.f32 "
        "{%0,%1,%2,%3}, {%4,%5,%6,%7}, {%8,%9}, {%0,%1,%2,%3};"
        : "+f"(c[0]), "+f"(c[1]), "+f"(c[2]), "+f"(c[3])
        : "r"(a0), "r"(a1), "r"(a2), "r"(a3), "r"(b0), "r"(b1));
}

// ---------------------------------------------------------------------------
// tf32 tensor GEMM: C[M x Nc] = act( (A (+A2)) @ W + bias )
// CTA: 128x128 tile, 256 threads = 8 warps (2 m x 4 n), warp tile 64x32.
// A: row-major [M,K] fp32 (rounded to tf32 on smem store).
// Wt: [Nc,K] K-major, pre-rounded tf32.
// ---------------------------------------------------------------------------
#define BK 32
#define LDA 36   // padded row stride (floats); 36*4=144B, 16B-aligned
template<int ACT, int HASA2>
__global__ void __launch_bounds__(256)
mma_gemm(const float* __restrict__ A, const float* __restrict__ A2,
         const float* __restrict__ Wt, const float* __restrict__ bias,
         float* __restrict__ C, int K, int Nc, int mtiles)
{
    __shared__ float As[128 * LDA];
    __shared__ float Bs[128 * LDA];

    const int tid = threadIdx.x;
    const int wid = tid >> 5, lane = tid & 31;
    const int g = lane >> 2, tg = lane & 3;
    const int wm = wid & 1, wn = wid >> 1;
    const int mt = blockIdx.x % mtiles;
    const int nt = blockIdx.x / mtiles;
    const int row0 = mt * 128, col0 = nt * 128;

    float acc[4][4][4];
#pragma unroll
    for (int i = 0; i < 4; i++)
#pragma unroll
        for (int j = 0; j < 4; j++)
#pragma unroll
            for (int k = 0; k < 4; k++) acc[i][j][k] = 0.f;

    const int nchunk = K / BK;
    for (int ch = 0; ch < nchunk; ch++) {
        const int k0 = ch * BK;
        // Load A tile (128 x 32) + tf32 round; B tile (128 x 32) pre-rounded.
#pragma unroll
        for (int i = 0; i < 4; i++) {
            int idx = tid + i * 256;          // 0..1023
            int r = idx >> 3, c4 = idx & 7;
            float4 v = *(const float4*)(A + (size_t)(row0 + r) * K + k0 + c4 * 4);
            if (HASA2) {
                float4 v2 = *(const float4*)(A2 + (size_t)(row0 + r) * K + k0 + c4 * 4);
                v.x += v2.x; v.y += v2.y; v.z += v2.z; v.w += v2.w;
            }
            uint4 t;
            asm("cvt.rna.tf32.f32 %0, %1;" : "=r"(t.x) : "f"(v.x));
            asm("cvt.rna.tf32.f32 %0, %1;" : "=r"(t.y) : "f"(v.y));
            asm("cvt.rna.tf32.f32 %0, %1;" : "=r"(t.z) : "f"(v.z));
            asm("cvt.rna.tf32.f32 %0, %1;" : "=r"(t.w) : "f"(v.w));
            *(uint4*)(&As[r * LDA + c4 * 4]) = t;
            uint4 b = *(const uint4*)(Wt + (size_t)(col0 + r) * K + k0 + c4 * 4);
            *(uint4*)(&Bs[r * LDA + c4 * 4]) = b;
        }
        __syncthreads();

#pragma unroll
        for (int ks = 0; ks < 4; ks++) {
            const int kk = ks * 8;
            uint32_t b[4][2];
#pragma unroll
            for (int nf = 0; nf < 4; nf++) {
                int n = wn * 32 + nf * 8 + g;
                b[nf][0] = __float_as_uint(Bs[n * LDA + kk + tg]);
                b[nf][1] = __float_as_uint(Bs[n * LDA + kk + tg + 4]);
            }
#pragma unroll
            for (int mf = 0; mf < 4; mf++) {
                int m = wm * 64 + mf * 16;
                uint32_t a0 = __float_as_uint(As[(m + g) * LDA + kk + tg]);
                uint32_t a1 = __float_as_uint(As[(m + 8 + g) * LDA + kk + tg]);
                uint32_t a2 = __float_as_uint(As[(m + g) * LDA + kk + tg + 4]);
                uint32_t a3 = __float_as_uint(As[(m + 8 + g) * LDA + kk + tg + 4]);
#pragma unroll
                for (int nf = 0; nf < 4; nf++)
                    mma_tf32(acc[mf][nf], a0, a1, a2, a3, b[nf][0], b[nf][1]);
            }
        }
        __syncthreads();
    }

    // Epilogue: bias (+relu), direct float2 stores.
#pragma unroll
    for (int mf = 0; mf < 4; mf++) {
#pragma unroll
        for (int nf = 0; nf < 4; nf++) {
            int row = row0 + wm * 64 + mf * 16 + g;
            int col = col0 + wn * 32 + nf * 8 + tg * 2;
            float b0 = bias[col], b1 = bias[col + 1];
            float2 o0, o1;
            o0.x = acc[mf][nf][0] + b0; o0.y = acc[mf][nf][1] + b1;
            o1.x = acc[mf][nf][2] + b0; o1.y = acc[mf][nf][3] + b1;
            if (ACT) {
                o0.x = fmaxf(o0.x, 0.f); o0.y = fmaxf(o0.y, 0.f);
                o1.x = fmaxf(o1.x, 0.f); o1.y = fmaxf(o1.y, 0.f);
            }
            *(float2*)(&C[(size_t)row * Nc + col]) = o0;
            *(float2*)(&C[(size_t)(row + 8) * Nc + col]) = o1;
        }
    }
}

// ---------------------------------------------------------------------------
// Deformable sampling with fused softmax.
// ---------------------------------------------------------------------------
__global__ void sample_kernel(const float* __restrict__ value,
                              const float* __restrict__ offs,
                              const float* __restrict__ logits,
                              const float* __restrict__ ref,
                              float* __restrict__ out)
{
    const int t = blockIdx.x;
    const int n = t / LQ;
    const int h = threadIdx.x >> 5;
    const int d = threadIdx.x & 31;

    float lg[16];
    const float* lp = logits + (size_t)t * 128 + h * 16;
    float mx = -1e30f;
#pragma unroll
    for (int j = 0; j < 16; j++) { lg[j] = lp[j]; mx = fmaxf(mx, lg[j]); }
    float ssum = 0.f;
#pragma unroll
    for (int j = 0; j < 16; j++) { lg[j] = expf(lg[j] - mx); ssum += lg[j]; }
    const float inv = 1.f / ssum;

    const float* op = offs + (size_t)t * DIM + h * (NLVL * NPT * 2);
    const int Hs[4] = {64, 32, 16, 8};
    const int St[4] = {0, 4096, 5120, 5376};

    float acc = 0.f;
#pragma unroll
    for (int l = 0; l < NLVL; l++) {
        const int H = Hs[l];
        const int W = Hs[l];
        const float fH = (float)H, fW = (float)W;
        const float invW = 1.f / fW, invH = 1.f / fH;
        const float refx = ref[((size_t)t * NLVL + l) * 2 + 0];
        const float refy = ref[((size_t)t * NLVL + l) * 2 + 1];
        const float* vbase = value + ((size_t)(n * LQ + St[l])) * DIM + h * HD + d;
#pragma unroll
        for (int p = 0; p < NPT; p++) {
            float ox = op[(l * NPT + p) * 2 + 0];
            float oy = op[(l * NPT + p) * 2 + 1];
            float xf = (refx + ox * invW) * fW - 0.5f;
            float yf = (refy + oy * invH) * fH - 0.5f;
            float x0f = floorf(xf), y0f = floorf(yf);
            int x0 = (int)x0f, y0 = (int)y0f;
            float wx1 = xf - x0f, wy1 = yf - y0f;
            float wx0 = 1.f - wx1, wy0 = 1.f - wy1;

            float v00 = 0.f, v01 = 0.f, v10 = 0.f, v11 = 0.f;
            bool xin0 = (x0 >= 0) & (x0 < W);
            bool xin1 = (x0 + 1 >= 0) & (x0 + 1 < W);
            bool yin0 = (y0 >= 0) & (y0 < H);
            bool yin1 = (y0 + 1 >= 0) & (y0 + 1 < H);
            if (yin0 && xin0) v00 = vbase[(size_t)(y0 * W + x0) * DIM];
            if (yin0 && xin1) v01 = vbase[(size_t)(y0 * W + x0 + 1) * DIM];
            if (yin1 && xin0) v10 = vbase[(size_t)((y0 + 1) * W + x0) * DIM];
            if (yin1 && xin1) v11 = vbase[(size_t)((y0 + 1) * W + x0 + 1) * DIM];

            float bil = (v00 * wx0 + v01 * wx1) * wy0 + (v10 * wx0 + v11 * wx1) * wy1;
            acc = fmaf(lg[l * NPT + p] * inv, bil, acc);
        }
    }
    out[(size_t)t * DIM + threadIdx.x] = acc;
}

// ---------------------------------------------------------------------------
// LayerNorm over 256: out = LN(a + b) * g + beta. One warp per token.
// ---------------------------------------------------------------------------
__global__ void ln_kernel(const float* __restrict__ a, const float* __restrict__ b,
                          const float* __restrict__ g, const float* __restrict__ beta,
                          float* __restrict__ out)
{
    const int t = blockIdx.x * 4 + (threadIdx.x >> 5);
    const int lane = threadIdx.x & 31;
    const float* pa = a + (size_t)t * DIM;
    const float* pb = b + (size_t)t * DIM;

    float v[8];
    float s = 0.f;
#pragma unroll
    for (int i = 0; i < 8; i++) {
        int c = lane + i * 32;
        v[i] = pa[c] + pb[c];
        s += v[i];
    }
#pragma unroll
    for (int o = 16; o; o >>= 1) s += __shfl_xor_sync(0xffffffffu, s, o);
    const float mean = s * (1.f / 256.f);
    float var = 0.f;
#pragma unroll
    for (int i = 0; i < 8; i++) { float dd = v[i] - mean; var += dd * dd; }
#pragma unroll
    for (int o = 16; o; o >>= 1) var += __shfl_xor_sync(0xffffffffu, var, o);
    const float rstd = rsqrtf(var * (1.f / 256.f) + 1e-5f);
#pragma unroll
    for (int i = 0; i < 8; i++) {
        int c = lane + i * 32;
        out[(size_t)t * DIM + c] = (v[i] - mean) * rstd * g[c] + beta[c];
    }
}

// ---------------------------------------------------------------------------
extern "C" void kernel_launch(void* const* d_in, const int* in_sizes, int n_in,
                              void* d_out, int out_size)
{
    const float* src  = (const float*)d_in[0];
    const float* pos  = (const float*)d_in[1];
    const float* refp = (const float*)d_in[2];
    const float* Wv   = (const float*)d_in[4];
    const float* bv   = (const float*)d_in[5];
    const float* Wo   = (const float*)d_in[6];
    const float* bo   = (const float*)d_in[7];
    const float* Wa   = (const float*)d_in[8];
    const float* ba   = (const float*)d_in[9];
    const float* Wout = (const float*)d_in[10];
    const float* bout = (const float*)d_in[11];
    const float* g1   = (const float*)d_in[12];
    const float* be1  = (const float*)d_in[13];
    const float* W1   = (const float*)d_in[14];
    const float* b1   = (const float*)d_in[15];
    const float* W2   = (const float*)d_in[16];
    const float* b2   = (const float*)d_in[17];
    const float* g2   = (const float*)d_in[18];
    const float* be2  = (const float*)d_in[19];
    float* out = (float*)d_out;

    float *pv, *poff, *pattn, *psamp, *psrc2, *px, *phid, *pffn;
    float *wtv, *wtoff, *wtattn, *wtout, *wt1, *wt2;
    cudaGetSymbolAddress((void**)&pv,    g_value);
    cudaGetSymbolAddress((void**)&poff,  g_off);
    cudaGetSymbolAddress((void**)&pattn, g_attn);
    cudaGetSymbolAddress((void**)&psamp, g_samp);
    cudaGetSymbolAddress((void**)&psrc2, g_src2);
    cudaGetSymbolAddress((void**)&px,    g_x);
    cudaGetSymbolAddress((void**)&phid,  g_hid);
    cudaGetSymbolAddress((void**)&pffn,  g_ffn);
    cudaGetSymbolAddress((void**)&wtv,   g_wtv);
    cudaGetSymbolAddress((void**)&wtoff, g_wtoff);
    cudaGetSymbolAddress((void**)&wtattn,g_wtattn);
    cudaGetSymbolAddress((void**)&wtout, g_wtout);
    cudaGetSymbolAddress((void**)&wt1,   g_wt1);
    cudaGetSymbolAddress((void**)&wt2,   g_wt2);

    // Pre-transpose weights to [N,K] tf32 (tiny)
    transpose_tf32<<<(256*256 + 255) / 256, 256>>>(Wv,   wtv,   256, 256);
    transpose_tf32<<<(256*256 + 255) / 256, 256>>>(Wo,   wtoff, 256, 256);
    transpose_tf32<<<(256*128 + 255) / 256, 256>>>(Wa,   wtattn,256, 128);
    transpose_tf32<<<(256*256 + 255) / 256, 256>>>(Wout, wtout, 256, 256);
    transpose_tf32<<<(256*1024 + 255) / 256, 256>>>(W1,  wt1,   256, 1024);
    transpose_tf32<<<(1024*256 + 255) / 256, 256>>>(W2,  wt2,  1024, 256);

    const int MT = TTOK / 128;  // 340 M-tiles

    // value = src @ Wv + bv
    mma_gemm<0, 0><<<MT * 2, 256>>>(src, nullptr, wtv, bv, pv, 256, 256, MT);
    // offsets = (src+pos) @ Woff + boff
    mma_gemm<0, 1><<<MT * 2, 256>>>(src, pos, wtoff, bo, poff, 256, 256, MT);
    // attn logits = (src+pos) @ Wattn + battn
    mma_gemm<0, 1><<<MT * 1, 256>>>(src, pos, wtattn, ba, pattn, 256, 128, MT);
    // deformable sampling (softmax fused)
    sample_kernel<<<TTOK, 256>>>(pv, poff, pattn, refp, psamp);
    // src2 = samp @ Wout + bout
    mma_gemm<0, 0><<<MT * 2, 256>>>(psamp, nullptr, wtout, bout, psrc2, 256, 256, MT);
    // x = LN1(src + src2)
    ln_kernel<<<TTOK / 4, 128>>>(src, psrc2, g1, be1, px);
    // hid = relu(x @ W1 + b1)
    mma_gemm<1, 0><<<MT * 8, 256>>>(px, nullptr, wt1, b1, phid, 256, 1024, MT);
    // ffn = hid @ W2 + b2
    mma_gemm<0, 0><<<MT * 2, 256>>>(phid, nullptr, wt2, b2, pffn, 1024, 256, MT);
    // out = LN2(x + ffn)
    ln_kernel<<<TTOK / 4, 128>>>(px, pffn, g2, be2, out);
}

// round 4
// speedup vs baseline: 2.7726x; 1.4137x over previous
#include <cuda_runtime.h>
#include <cstdint>
#include <math.h>

// Problem constants (static per reference)
#define NBATCH 8
#define LQ     5440
#define TTOK   (NBATCH*LQ)      // 43520
#define DIM    256
#define NHEAD  8
#define HD     32
#define NLVL   4
#define NPT    4
#define DFF    1024

// Scratch (device globals; no runtime allocation)
__device__ float g_value[(size_t)TTOK*DIM];
__device__ float g_off  [(size_t)TTOK*DIM];
__device__ float g_attn [(size_t)TTOK*128];
__device__ float g_samp [(size_t)TTOK*DIM];
__device__ float g_src2 [(size_t)TTOK*DIM];
__device__ float g_x    [(size_t)TTOK*DIM];
__device__ float g_xr   [(size_t)TTOK*DIM];
__device__ float g_hid  [(size_t)TTOK*DFF];
__device__ float g_ffn  [(size_t)TTOK*DIM];
__device__ float g_srcr [(size_t)TTOK*DIM];
__device__ float g_qr   [(size_t)TTOK*DIM];
// Transposed (N-major -> [N][K]) tf32-rounded weights
__device__ float g_wtv  [256*256];
__device__ float g_wtoff[256*256];
__device__ float g_wtattn[128*256];
__device__ float g_wtout[256*256];
__device__ float g_wt1  [1024*256];
__device__ float g_wt2  [256*1024];

// ---------------------------------------------------------------------------
// Helpers
// ---------------------------------------------------------------------------
__device__ __forceinline__ uint32_t smem_u32(const void* p) {
    uint32_t a;
    asm("{ .reg .u64 t; cvta.to.shared.u64 t, %1; cvt.u32.u64 %0, t; }" : "=r"(a) : "l"(p));
    return a;
}
__device__ __forceinline__ uint32_t rna(float v) {
    uint32_t t; asm("cvt.rna.tf32.f32 %0, %1;" : "=r"(t) : "f"(v)); return t;
}
__device__ __forceinline__ void cpasync16(uint32_t dst, const float* src) {
    asm volatile("cp.async.cg.shared.global [%0], [%1], 16;" :: "r"(dst), "l"(src));
}
#define CP_COMMIT() asm volatile("cp.async.commit_group;" ::: "memory")
#define CP_WAIT1()  asm volatile("cp.async.wait_group 1;" ::: "memory")

__device__ __forceinline__ void mma_tf32(float* c, uint32_t a0, uint32_t a1,
                                         uint32_t a2, uint32_t a3,
                                         uint32_t b0, uint32_t b1) {
    asm volatile(
        "mma.sync.aligned.m16n8k8.row.col.f32.tf32.tf32.f32 "
        "{%0,%1,%2,%3}, {%4,%5,%6,%7}, {%8,%9}, {%0,%1,%2,%3};"
        : "+f"(c[0]), "+f"(c[1]), "+f"(c[2]), "+f"(c[3])
        : "r"(a0), "r"(a1), "r"(a2), "r"(a3), "r"(b0), "r"(b1));
}

// Swizzled offset in a 128x32 tile (floats): granule = 16B, XOR with row&7.
__device__ __forceinline__ int swoff(int r, int c) {
    return r * 32 + ((((c >> 2) ^ (r & 7))) << 2) + (c & 3);
}

// ---------------------------------------------------------------------------
// Weight transpose + tf32 round: Wt[n*K + k] = rna_tf32(W[k*N + n])
// ---------------------------------------------------------------------------
__global__ void transpose_tf32(const float* __restrict__ W, float* __restrict__ Wt,
                               int K, int N) {
    int idx = blockIdx.x * 256 + threadIdx.x;
    if (idx < K * N) {
        int n = idx / K, k = idx - n * K;
        ((uint32_t*)Wt)[idx] = rna(W[(size_t)k * N + n]);
    }
}

// ---------------------------------------------------------------------------
// Pre-round activations: sr = rna(src), qr = rna(src + pos)
// ---------------------------------------------------------------------------
__global__ void preround(const float4* __restrict__ src, const float4* __restrict__ pos,
                         uint4* __restrict__ sr, uint4* __restrict__ qr) {
    int idx = blockIdx.x * 256 + threadIdx.x;
    float4 s = src[idx], p = pos[idx];
    uint4 a, q;
    a.x = rna(s.x); a.y = rna(s.y); a.z = rna(s.z); a.w = rna(s.w);
    q.x = rna(s.x + p.x); q.y = rna(s.y + p.y); q.z = rna(s.z + p.z); q.w = rna(s.w + p.w);
    sr[idx] = a; qr[idx] = q;
}

// ---------------------------------------------------------------------------
// tf32 tensor GEMM, cp.async double-buffered.
// C[M x Nc] = act( A @ Wt^T + bias ), A pre-rounded tf32 [M,K] row-major,
// Wt [Nc,K] K-major pre-rounded. CTA: 128x128 tile, 8 warps (2m x 4n).
// Dynamic smem: 2 stages x (A 16KB + B 16KB) = 64KB.
// ---------------------------------------------------------------------------
#define BK 32
template<int ACT, int RND>
__global__ void __launch_bounds__(256)
mma_gemm(const float* __restrict__ A, const float* __restrict__ Wt,
         const float* __restrict__ bias, float* __restrict__ C,
         int K, int Nc, int mtiles)
{
    extern __shared__ float smem[];
    // layout (floats): A st0 [0,4096) A st1 [4096,8192) B st0 [8192,12288) B st1 [12288,16384)
    const uint32_t sbase = smem_u32(smem);

    const int tid = threadIdx.x;
    const int wid = tid >> 5, lane = tid & 31;
    const int g = lane >> 2, tg = lane & 3;
    const int wm = wid & 1, wn = wid >> 1;
    const int mt = blockIdx.x % mtiles;
    const int nt = blockIdx.x / mtiles;
    const int row0 = mt * 128, col0 = nt * 128;

    const int r_ld = tid >> 1;              // 0..127 (each thread: 2 rows? no — see below)
    float acc[4][4][4];
#pragma unroll
    for (int i = 0; i < 4; i++)
#pragma unroll
        for (int j = 0; j < 4; j++)
#pragma unroll
            for (int k = 0; k < 4; k++) acc[i][j][k] = 0.f;

    // Per-thread copy assignment: 1024 granules per matrix per chunk, 256 thr -> 4 each.
    // idx = tid + i*256 ; r = idx>>3, gc = idx&7.
    auto load_chunk = [&](int k0, int st) {
#pragma unroll
        for (int i = 0; i < 4; i++) {
            int idx = tid + i * 256;
            int r = idx >> 3, gc = idx & 7;
            int sw = ((gc ^ (r & 7)) << 2);
            cpasync16(sbase + (uint32_t)(st * 4096 + r * 32 + sw) * 4,
                      A + (size_t)(row0 + r) * K + k0 + gc * 4);
            cpasync16(sbase + (uint32_t)(8192 + st * 4096 + r * 32 + sw) * 4,
                      Wt + (size_t)(col0 + r) * K + k0 + gc * 4);
        }
    };

    const int nchunk = K / BK;
    load_chunk(0, 0);
    CP_COMMIT();

    for (int ch = 0; ch < nchunk; ch++) {
        if (ch + 1 < nchunk) load_chunk((ch + 1) * BK, (ch + 1) & 1);
        CP_COMMIT();
        CP_WAIT1();
        __syncthreads();

        const float* As = smem + (ch & 1) * 4096;
        const float* Bs = smem + 8192 + (ch & 1) * 4096;
#pragma unroll
        for (int ks = 0; ks < 4; ks++) {
            const int kk = ks * 8;
            uint32_t b[4][2];
#pragma unroll
            for (int nf = 0; nf < 4; nf++) {
                int n = wn * 32 + nf * 8 + g;
                b[nf][0] = __float_as_uint(Bs[swoff(n, kk + tg)]);
                b[nf][1] = __float_as_uint(Bs[swoff(n, kk + tg + 4)]);
            }
#pragma unroll
            for (int mf = 0; mf < 4; mf++) {
                int m = wm * 64 + mf * 16;
                uint32_t a0 = __float_as_uint(As[swoff(m + g, kk + tg)]);
                uint32_t a1 = __float_as_uint(As[swoff(m + 8 + g, kk + tg)]);
                uint32_t a2 = __float_as_uint(As[swoff(m + g, kk + tg + 4)]);
                uint32_t a3 = __float_as_uint(As[swoff(m + 8 + g, kk + tg + 4)]);
#pragma unroll
                for (int nf = 0; nf < 4; nf++)
                    mma_tf32(acc[mf][nf], a0, a1, a2, a3, b[nf][0], b[nf][1]);
            }
        }
        __syncthreads();
    }

    // Epilogue: bias (+relu) (+tf32 round), float2 stores.
#pragma unroll
    for (int mf = 0; mf < 4; mf++) {
#pragma unroll
        for (int nf = 0; nf < 4; nf++) {
            int row = row0 + wm * 64 + mf * 16 + g;
            int col = col0 + wn * 32 + nf * 8 + tg * 2;
            float b0 = bias[col], b1 = bias[col + 1];
            float o[4];
            o[0] = acc[mf][nf][0] + b0; o[1] = acc[mf][nf][1] + b1;
            o[2] = acc[mf][nf][2] + b0; o[3] = acc[mf][nf][3] + b1;
            if (ACT) {
#pragma unroll
                for (int i = 0; i < 4; i++) o[i] = fmaxf(o[i], 0.f);
            }
            if (RND) {
#pragma unroll
                for (int i = 0; i < 4; i++) o[i] = __uint_as_float(rna(o[i]));
            }
            *(float2*)(&C[(size_t)row * Nc + col]) = make_float2(o[0], o[1]);
            *(float2*)(&C[(size_t)(row + 8) * Nc + col]) = make_float2(o[2], o[3]);
        }
    }
}

// ---------------------------------------------------------------------------
// Deformable sampling with fused softmax. 4 tokens/block, 64 threads/token
// (8 heads x 8 threads, float4 per thread). Output tf32-rounded.
// ---------------------------------------------------------------------------
__global__ void __launch_bounds__(256)
sample_kernel(const float* __restrict__ value,
              const float* __restrict__ offs,
              const float* __restrict__ logits,
              const float* __restrict__ ref,
              uint4* __restrict__ out)
{
    const int sub = threadIdx.x >> 6;
    const int t = blockIdx.x * 4 + sub;
    const int n = t / LQ;
    const int t6 = threadIdx.x & 63;
    const int h = t6 >> 3;
    const int d4 = t6 & 7;

    // Softmax over the 16 (level,point) logits for this (token, head).
    float lg[16];
    const float* lp = logits + (size_t)t * 128 + h * 16;
    float mx = -1e30f;
#pragma unroll
    for (int j = 0; j < 16; j++) { lg[j] = lp[j]; mx = fmaxf(mx, lg[j]); }
    float ssum = 0.f;
#pragma unroll
    for (int j = 0; j < 16; j++) { lg[j] = expf(lg[j] - mx); ssum += lg[j]; }
    const float inv = 1.f / ssum;

    const float* op = offs + (size_t)t * DIM + h * (NLVL * NPT * 2);
    const int Hs[4] = {64, 32, 16, 8};
    const int St[4] = {0, 4096, 5120, 5376};

    float4 acc = make_float4(0.f, 0.f, 0.f, 0.f);
#pragma unroll
    for (int l = 0; l < NLVL; l++) {
        const int H = Hs[l];
        const int W = Hs[l];
        const float fH = (float)H, fW = (float)W;
        const float invW = 1.f / fW, invH = 1.f / fH;
        const float refx = ref[((size_t)t * NLVL + l) * 2 + 0];
        const float refy = ref[((size_t)t * NLVL + l) * 2 + 1];
        const float4* vbase = (const float4*)(value + ((size_t)(n * LQ + St[l])) * DIM + h * HD) + d4;
#pragma unroll
        for (int p = 0; p < NPT; p++) {
            float ox = op[(l * NPT + p) * 2 + 0];
            float oy = op[(l * NPT + p) * 2 + 1];
            float xf = (refx + ox * invW) * fW - 0.5f;
            float yf = (refy + oy * invH) * fH - 0.5f;
            float x0f = floorf(xf), y0f = floorf(yf);
            int x0 = (int)x0f, y0 = (int)y0f;
            float wx1 = xf - x0f, wy1 = yf - y0f;
            float wx0 = 1.f - wx1, wy0 = 1.f - wy1;
            float w = lg[l * NPT + p] * inv;

            bool xin0 = (x0 >= 0) & (x0 < W);
            bool xin1 = (x0 + 1 >= 0) & (x0 + 1 < W);
            bool yin0 = (y0 >= 0) & (y0 < H);
            bool yin1 = (y0 + 1 >= 0) & (y0 + 1 < H);
            float4 v00 = make_float4(0,0,0,0), v01 = v00, v10 = v00, v11 = v00;
            if (yin0 && xin0) v00 = vbase[(size_t)(y0 * W + x0) * (DIM/4)];
            if (yin0 && xin1) v01 = vbase[(size_t)(y0 * W + x0 + 1) * (DIM/4)];
            if (yin1 && xin0) v10 = vbase[(size_t)((y0 + 1) * W + x0) * (DIM/4)];
            if (yin1 && xin1) v11 = vbase[(size_t)((y0 + 1) * W + x0 + 1) * (DIM/4)];

            float c00 = w * wy0 * wx0, c01 = w * wy0 * wx1;
            float c10 = w * wy1 * wx0, c11 = w * wy1 * wx1;
            acc.x = fmaf(v00.x, c00, fmaf(v01.x, c01, fmaf(v10.x, c10, fmaf(v11.x, c11, acc.x))));
            acc.y = fmaf(v00.y, c00, fmaf(v01.y, c01, fmaf(v10.y, c10, fmaf(v11.y, c11, acc.y))));
            acc.z = fmaf(v00.z, c00, fmaf(v01.z, c01, fmaf(v10.z, c10, fmaf(v11.z, c11, acc.z))));
            acc.w = fmaf(v00.w, c00, fmaf(v01.w, c01, fmaf(v10.w, c10, fmaf(v11.w, c11, acc.w))));
        }
    }
    uint4 o;
    o.x = rna(acc.x); o.y = rna(acc.y); o.z = rna(acc.z); o.w = rna(acc.w);
    out[(size_t)t * (DIM/4) + h * 8 + d4] = o;
}

// ---------------------------------------------------------------------------
// LayerNorm over 256: out = LN(a + b) * g + beta. One warp per token.
// Optionally also writes a tf32-rounded copy (for downstream GEMM).
// ---------------------------------------------------------------------------
__global__ void ln_kernel(const float* __restrict__ a, const float* __restrict__ b,
                          const float* __restrict__ g, const float* __restrict__ beta,
                          float* __restrict__ out, float* __restrict__ out_r)
{
    const int t = blockIdx.x * 4 + (threadIdx.x >> 5);
    const int lane = threadIdx.x & 31;
    const float* pa = a + (size_t)t * DIM;
    const float* pb = b + (size_t)t * DIM;

    float v[8];
    float s = 0.f;
#pragma unroll
    for (int i = 0; i < 8; i++) {
        int c = lane + i * 32;
        v[i] = pa[c] + pb[c];
        s += v[i];
    }
#pragma unroll
    for (int o = 16; o; o >>= 1) s += __shfl_xor_sync(0xffffffffu, s, o);
    const float mean = s * (1.f / 256.f);
    float var = 0.f;
#pragma unroll
    for (int i = 0; i < 8; i++) { float dd = v[i] - mean; var += dd * dd; }
#pragma unroll
    for (int o = 16; o; o >>= 1) var += __shfl_xor_sync(0xffffffffu, var, o);
    const float rstd = rsqrtf(var * (1.f / 256.f) + 1e-5f);
#pragma unroll
    for (int i = 0; i < 8; i++) {
        int c = lane + i * 32;
        float y = (v[i] - mean) * rstd * g[c] + beta[c];
        out[(size_t)t * DIM + c] = y;
        if (out_r) out_r[(size_t)t * DIM + c] = __uint_as_float(rna(y));
    }
}

// ---------------------------------------------------------------------------
extern "C" void kernel_launch(void* const* d_in, const int* in_sizes, int n_in,
                              void* d_out, int out_size)
{
    const float* src  = (const float*)d_in[0];
    const float* pos  = (const float*)d_in[1];
    const float* refp = (const float*)d_in[2];
    const float* Wv   = (const float*)d_in[4];
    const float* bv   = (const float*)d_in[5];
    const float* Wo   = (const float*)d_in[6];
    const float* bo   = (const float*)d_in[7];
    const float* Wa   = (const float*)d_in[8];
    const float* ba   = (const float*)d_in[9];
    const float* Wout = (const float*)d_in[10];
    const float* bout = (const float*)d_in[11];
    const float* g1   = (const float*)d_in[12];
    const float* be1  = (const float*)d_in[13];
    const float* W1   = (const float*)d_in[14];
    const float* b1   = (const float*)d_in[15];
    const float* W2   = (const float*)d_in[16];
    const float* b2   = (const float*)d_in[17];
    const float* g2   = (const float*)d_in[18];
    const float* be2  = (const float*)d_in[19];
    float* out = (float*)d_out;

    float *pv, *poff, *pattn, *psamp, *psrc2, *px, *pxr, *phid, *pffn, *psrcr, *pqr;
    float *wtv, *wtoff, *wtattn, *wtout, *wt1, *wt2;
    cudaGetSymbolAddress((void**)&pv,    g_value);
    cudaGetSymbolAddress((void**)&poff,  g_off);
    cudaGetSymbolAddress((void**)&pattn, g_attn);
    cudaGetSymbolAddress((void**)&psamp, g_samp);
    cudaGetSymbolAddress((void**)&psrc2, g_src2);
    cudaGetSymbolAddress((void**)&px,    g_x);
    cudaGetSymbolAddress((void**)&pxr,   g_xr);
    cudaGetSymbolAddress((void**)&phid,  g_hid);
    cudaGetSymbolAddress((void**)&pffn,  g_ffn);
    cudaGetSymbolAddress((void**)&psrcr, g_srcr);
    cudaGetSymbolAddress((void**)&pqr,   g_qr);
    cudaGetSymbolAddress((void**)&wtv,   g_wtv);
    cudaGetSymbolAddress((void**)&wtoff, g_wtoff);
    cudaGetSymbolAddress((void**)&wtattn,g_wtattn);
    cudaGetSymbolAddress((void**)&wtout, g_wtout);
    cudaGetSymbolAddress((void**)&wt1,   g_wt1);
    cudaGetSymbolAddress((void**)&wt2,   g_wt2);

    const int DSM = 65536;
    cudaFuncSetAttribute(mma_gemm<0,0>, cudaFuncAttributeMaxDynamicSharedMemorySize, DSM);
    cudaFuncSetAttribute(mma_gemm<1,1>, cudaFuncAttributeMaxDynamicSharedMemorySize, DSM);

    // Weight prep (tiny) + activation pre-round
    transpose_tf32<<<(256*256 + 255) / 256, 256>>>(Wv,   wtv,   256, 256);
    transpose_tf32<<<(256*256 + 255) / 256, 256>>>(Wo,   wtoff, 256, 256);
    transpose_tf32<<<(256*128 + 255) / 256, 256>>>(Wa,   wtattn,256, 128);
    transpose_tf32<<<(256*256 + 255) / 256, 256>>>(Wout, wtout, 256, 256);
    transpose_tf32<<<(256*1024 + 255) / 256, 256>>>(W1,  wt1,   256, 1024);
    transpose_tf32<<<(1024*256 + 255) / 256, 256>>>(W2,  wt2,  1024, 256);
    preround<<<(TTOK*DIM/4) / 256, 256>>>((const float4*)src, (const float4*)pos,
                                          (uint4*)psrcr, (uint4*)pqr);

    const int MT = TTOK / 128;  // 340 M-tiles

    // value = src @ Wv + bv
    mma_gemm<0,0><<<MT * 2, 256, DSM>>>(psrcr, wtv, bv, pv, 256, 256, MT);
    // offsets = (src+pos) @ Woff + boff
    mma_gemm<0,0><<<MT * 2, 256, DSM>>>(pqr, wtoff, bo, poff, 256, 256, MT);
    // attn logits = (src+pos) @ Wattn + battn
    mma_gemm<0,0><<<MT * 1, 256, DSM>>>(pqr, wtattn, ba, pattn, 256, 128, MT);
    // deformable sampling (softmax fused; writes tf32-rounded samp)
    sample_kernel<<<TTOK / 4, 256>>>(pv, poff, pattn, refp, (uint4*)psamp);
    // src2 = samp @ Wout + bout
    mma_gemm<0,0><<<MT * 2, 256, DSM>>>(psamp, wtout, bout, psrc2, 256, 256, MT);
    // x = LN1(src + src2), plus rounded copy for FFN1
    ln_kernel<<<TTOK / 4, 128>>>(src, psrc2, g1, be1, px, pxr);
    // hid = relu(x @ W1 + b1), rounded for FFN2
    mma_gemm<1,1><<<MT * 8, 256, DSM>>>(pxr, wt1, b1, phid, 256, 1024, MT);
    // ffn = hid @ W2 + b2
    mma_gemm<0,0><<<MT * 2, 256, DSM>>>(phid, wt2, b2, pffn, 1024, 256, MT);
    // out = LN2(x + ffn)
    ln_kernel<<<TTOK / 4, 128>>>(px, pffn, g2, be2, out, nullptr);
}

// round 5
// speedup vs baseline: 3.1767x; 1.1457x over previous
#include <cuda_runtime.h>
#include <cuda_bf16.h>
#include <cstdint>
#include <math.h>

// Problem constants (static per reference)
#define NBATCH 8
#define LQ     5440
#define TTOK   (NBATCH*LQ)      // 43520
#define DIM    256
#define NHEAD  8
#define HD     32
#define NLVL   4
#define NPT    4
#define DFF    1024

// Scratch (device globals; no runtime allocation)
__device__ __nv_bfloat16 g_valbf[(size_t)TTOK*DIM];
__device__ float g_offattn[(size_t)TTOK*384];
__device__ float g_samp [(size_t)TTOK*DIM];
__device__ float g_src2 [(size_t)TTOK*DIM];
__device__ float g_x    [(size_t)TTOK*DIM];
__device__ float g_hid  [(size_t)TTOK*DFF];
__device__ float g_ffn  [(size_t)TTOK*DIM];
__device__ float g_qr   [(size_t)TTOK*DIM];
// Transposed (N-major -> [N][K]) tf32-rounded weights
__device__ float g_wtv  [256*256];
__device__ float g_wtoa [384*256];
__device__ float g_wtout[256*256];
__device__ float g_wt1  [1024*256];
__device__ float g_wt2  [256*1024];
__device__ float g_boa  [384];

// ---------------------------------------------------------------------------
// Helpers
// ---------------------------------------------------------------------------
__device__ __forceinline__ uint32_t smem_u32(const void* p) {
    uint32_t a;
    asm("{ .reg .u64 t; cvta.to.shared.u64 t, %1; cvt.u32.u64 %0, t; }" : "=r"(a) : "l"(p));
    return a;
}
__device__ __forceinline__ uint32_t rna(float v) {
    uint32_t t; asm("cvt.rna.tf32.f32 %0, %1;" : "=r"(t) : "f"(v)); return t;
}
__device__ __forceinline__ void cpasync16(uint32_t dst, const float* src) {
    asm volatile("cp.async.cg.shared.global [%0], [%1], 16;" :: "r"(dst), "l"(src));
}
#define CP_COMMIT() asm volatile("cp.async.commit_group;" ::: "memory")
#define CP_WAIT1()  asm volatile("cp.async.wait_group 1;" ::: "memory")

__device__ __forceinline__ void mma_tf32(float* c, uint32_t a0, uint32_t a1,
                                         uint32_t a2, uint32_t a3,
                                         uint32_t b0, uint32_t b1) {
    asm volatile(
        "mma.sync.aligned.m16n8k8.row.col.f32.tf32.tf32.f32 "
        "{%0,%1,%2,%3}, {%4,%5,%6,%7}, {%8,%9}, {%0,%1,%2,%3};"
        : "+f"(c[0]), "+f"(c[1]), "+f"(c[2]), "+f"(c[3])
        : "r"(a0), "r"(a1), "r"(a2), "r"(a3), "r"(b0), "r"(b1));
}

// Swizzled offset in a 128x32 tile (floats): granule = 16B, XOR with row&7.
__device__ __forceinline__ int swoff(int r, int c) {
    return r * 32 + ((((c >> 2) ^ (r & 7))) << 2) + (c & 3);
}

// ---------------------------------------------------------------------------
// Weight transpose + tf32 round: Wt[n*K + k] = rna_tf32(W[k*N + n])
// ---------------------------------------------------------------------------
__global__ void transpose_tf32(const float* __restrict__ W, float* __restrict__ Wt,
                               int K, int N) {
    int idx = blockIdx.x * 256 + threadIdx.x;
    if (idx < K * N) {
        int n = idx / K, k = idx - n * K;
        ((uint32_t*)Wt)[idx] = rna(W[(size_t)k * N + n]);
    }
}

// Concat biases: boa = [bo(256) | ba(128)]
__global__ void concat_bias(const float* __restrict__ bo, const float* __restrict__ ba,
                            float* __restrict__ boa) {
    int i = threadIdx.x;
    boa[i] = (i < 256) ? bo[i] : ba[i - 256];
}

// qr = rna(src + pos)
__global__ void preround_q(const float4* __restrict__ src, const float4* __restrict__ pos,
                           uint4* __restrict__ qr) {
    int idx = blockIdx.x * 256 + threadIdx.x;
    float4 s = src[idx], p = pos[idx];
    uint4 q;
    q.x = rna(s.x + p.x); q.y = rna(s.y + p.y); q.z = rna(s.z + p.z); q.w = rna(s.w + p.w);
    qr[idx] = q;
}

// ---------------------------------------------------------------------------
// tf32 tensor GEMM, cp.async 3-stage pipeline.
// C[M x Nc] = act( A @ Wt^T + bias ). A row-major [M,K] fp32; RNDA rounds A
// fragments in-register (A may be raw fp32). Wt [Nc,K] K-major pre-rounded.
// CTA: 128x128 tile, 8 warps (2m x 4n). Smem: 3 stages x (16KB A + 16KB B).
// OBF: write bf16 output (C16); RND: tf32-round fp32 output.
// ---------------------------------------------------------------------------
#define BK 32
template<int ACT, int RND, int RNDA, int OBF>
__global__ void __launch_bounds__(256, 2)
mma_gemm(const float* __restrict__ A, const float* __restrict__ Wt,
         const float* __restrict__ bias, float* __restrict__ C,
         __nv_bfloat16* __restrict__ C16, int K, int Nc, int mtiles)
{
    extern __shared__ float smem[];
    // floats: A stages [0,4096),[4096,8192),[8192,12288); B stages +12288
    const uint32_t sbase = smem_u32(smem);

    const int tid = threadIdx.x;
    const int wid = tid >> 5, lane = tid & 31;
    const int g = lane >> 2, tg = lane & 3;
    const int wm = wid & 1, wn = wid >> 1;
    const int mt = blockIdx.x % mtiles;
    const int nt = blockIdx.x / mtiles;
    const int row0 = mt * 128, col0 = nt * 128;

    float acc[4][4][4];
#pragma unroll
    for (int i = 0; i < 4; i++)
#pragma unroll
        for (int j = 0; j < 4; j++)
#pragma unroll
            for (int k = 0; k < 4; k++) acc[i][j][k] = 0.f;

    auto load_chunk = [&](int k0, int st) {
#pragma unroll
        for (int i = 0; i < 4; i++) {
            int idx = tid + i * 256;
            int r = idx >> 3, gc = idx & 7;
            int sw = ((gc ^ (r & 7)) << 2);
            cpasync16(sbase + (uint32_t)(st * 4096 + r * 32 + sw) * 4,
                      A + (size_t)(row0 + r) * K + k0 + gc * 4);
            cpasync16(sbase + (uint32_t)(12288 + st * 4096 + r * 32 + sw) * 4,
                      Wt + (size_t)(col0 + r) * K + k0 + gc * 4);
        }
    };

    const int nchunk = K / BK;
    load_chunk(0, 0);
    CP_COMMIT();
    load_chunk(BK, 1);
    CP_COMMIT();

    for (int ch = 0; ch < nchunk; ch++) {
        CP_WAIT1();
        __syncthreads();
        if (ch + 2 < nchunk) load_chunk((ch + 2) * BK, (ch + 2) % 3);
        CP_COMMIT();

        const float* As = smem + (ch % 3) * 4096;
        const float* Bs = smem + 12288 + (ch % 3) * 4096;
#pragma unroll
        for (int ks = 0; ks < 4; ks++) {
            const int kk = ks * 8;
            uint32_t b[4][2];
#pragma unroll
            for (int nf = 0; nf < 4; nf++) {
                int n = wn * 32 + nf * 8 + g;
                b[nf][0] = __float_as_uint(Bs[swoff(n, kk + tg)]);
                b[nf][1] = __float_as_uint(Bs[swoff(n, kk + tg + 4)]);
            }
#pragma unroll
            for (int mf = 0; mf < 4; mf++) {
                int m = wm * 64 + mf * 16;
                uint32_t a0 = __float_as_uint(As[swoff(m + g, kk + tg)]);
                uint32_t a1 = __float_as_uint(As[swoff(m + 8 + g, kk + tg)]);
                uint32_t a2 = __float_as_uint(As[swoff(m + g, kk + tg + 4)]);
                uint32_t a3 = __float_as_uint(As[swoff(m + 8 + g, kk + tg + 4)]);
                if (RNDA) {
                    a0 = rna(__uint_as_float(a0)); a1 = rna(__uint_as_float(a1));
                    a2 = rna(__uint_as_float(a2)); a3 = rna(__uint_as_float(a3));
                }
#pragma unroll
                for (int nf = 0; nf < 4; nf++)
                    mma_tf32(acc[mf][nf], a0, a1, a2, a3, b[nf][0], b[nf][1]);
            }
        }
    }

    // Epilogue
#pragma unroll
    for (int mf = 0; mf < 4; mf++) {
#pragma unroll
        for (int nf = 0; nf < 4; nf++) {
            int row = row0 + wm * 64 + mf * 16 + g;
            int col = col0 + wn * 32 + nf * 8 + tg * 2;
            float b0 = bias[col], b1 = bias[col + 1];
            float o[4];
            o[0] = acc[mf][nf][0] + b0; o[1] = acc[mf][nf][1] + b1;
            o[2] = acc[mf][nf][2] + b0; o[3] = acc[mf][nf][3] + b1;
            if (ACT) {
#pragma unroll
                for (int i = 0; i < 4; i++) o[i] = fmaxf(o[i], 0.f);
            }
            if (OBF) {
                *(__nv_bfloat162*)(&C16[(size_t)row * Nc + col]) =
                    __float22bfloat162_rn(make_float2(o[0], o[1]));
                *(__nv_bfloat162*)(&C16[(size_t)(row + 8) * Nc + col]) =
                    __float22bfloat162_rn(make_float2(o[2], o[3]));
            } else {
                if (RND) {
#pragma unroll
                    for (int i = 0; i < 4; i++) o[i] = __uint_as_float(rna(o[i]));
                }
                *(float2*)(&C[(size_t)row * Nc + col]) = make_float2(o[0], o[1]);
                *(float2*)(&C[(size_t)(row + 8) * Nc + col]) = make_float2(o[2], o[3]);
            }
        }
    }
}

// ---------------------------------------------------------------------------
// Deformable sampling with fused softmax. Warp per token: 8 heads x 4 lanes,
// 8 dims (one uint4 of bf16) per lane. Value in bf16. Output tf32-rounded.
// ---------------------------------------------------------------------------
__global__ void __launch_bounds__(256)
sample_kernel(const __nv_bfloat16* __restrict__ valbf,
              const float* __restrict__ offattn,
              const float* __restrict__ ref,
              float* __restrict__ samp)
{
    const int t = blockIdx.x * 8 + (threadIdx.x >> 5);
    const int lane = threadIdx.x & 31;
    const int h = lane >> 2;
    const int d8 = lane & 3;
    const int n = t / LQ;

    const float* rowp = offattn + (size_t)t * 384;
    const float* lp = rowp + 256 + h * 16;
    const float* op = rowp + h * 32;

    // Softmax over 16 (level,point) logits for this (token, head).
    float lg[16];
    float mx = -1e30f;
#pragma unroll
    for (int j = 0; j < 16; j++) { lg[j] = lp[j]; mx = fmaxf(mx, lg[j]); }
    float ssum = 0.f;
#pragma unroll
    for (int j = 0; j < 16; j++) { lg[j] = expf(lg[j] - mx); ssum += lg[j]; }
    const float inv = 1.f / ssum;

    const int Hs[4] = {64, 32, 16, 8};
    const int St[4] = {0, 4096, 5120, 5376};

    float acc[8];
#pragma unroll
    for (int i = 0; i < 8; i++) acc[i] = 0.f;

#pragma unroll
    for (int l = 0; l < NLVL; l++) {
        const int H = Hs[l];
        const int W = Hs[l];
        const float fH = (float)H, fW = (float)W;
        const float invW = 1.f / fW, invH = 1.f / fH;
        const float refx = ref[((size_t)t * NLVL + l) * 2 + 0];
        const float refy = ref[((size_t)t * NLVL + l) * 2 + 1];
        const uint4* vb = (const uint4*)(valbf + ((size_t)(n * LQ + St[l])) * DIM + h * HD + d8 * 8);
#pragma unroll
        for (int p = 0; p < NPT; p++) {
            float ox = op[(l * NPT + p) * 2 + 0];
            float oy = op[(l * NPT + p) * 2 + 1];
            float xf = (refx + ox * invW) * fW - 0.5f;
            float yf = (refy + oy * invH) * fH - 0.5f;
            float x0f = floorf(xf), y0f = floorf(yf);
            int x0 = (int)x0f, y0 = (int)y0f;
            float wx1 = xf - x0f, wy1 = yf - y0f;
            float wx0 = 1.f - wx1, wy0 = 1.f - wy1;
            float w = lg[l * NPT + p] * inv;

            bool xin0 = (x0 >= 0) & (x0 < W);
            bool xin1 = (x0 + 1 >= 0) & (x0 + 1 < W);
            bool yin0 = (y0 >= 0) & (y0 < H);
            bool yin1 = (y0 + 1 >= 0) & (y0 + 1 < H);

            float cw[4] = { w * wy0 * wx0, w * wy0 * wx1, w * wy1 * wx0, w * wy1 * wx1 };
            bool vld[4] = { yin0 && xin0, yin0 && xin1, yin1 && xin0, yin1 && xin1 };
            int  idx[4] = { y0 * W + x0, y0 * W + x0 + 1, (y0 + 1) * W + x0, (y0 + 1) * W + x0 + 1 };
#pragma unroll
            for (int cnr = 0; cnr < 4; cnr++) {
                uint4 u = make_uint4(0u, 0u, 0u, 0u);
                if (vld[cnr]) u = vb[(size_t)idx[cnr] * (DIM / 8)];
                const __nv_bfloat162* q2 = (const __nv_bfloat162*)&u;
                float c = cw[cnr];
#pragma unroll
                for (int j = 0; j < 4; j++) {
                    float2 f = __bfloat1622float2(q2[j]);
                    acc[2 * j + 0] = fmaf(f.x, c, acc[2 * j + 0]);
                    acc[2 * j + 1] = fmaf(f.y, c, acc[2 * j + 1]);
                }
            }
        }
    }
    uint4 o0, o1;
    o0.x = rna(acc[0]); o0.y = rna(acc[1]); o0.z = rna(acc[2]); o0.w = rna(acc[3]);
    o1.x = rna(acc[4]); o1.y = rna(acc[5]); o1.z = rna(acc[6]); o1.w = rna(acc[7]);
    uint4* outp = (uint4*)(samp + (size_t)t * DIM + h * HD + d8 * 8);
    outp[0] = o0; outp[1] = o1;
}

// ---------------------------------------------------------------------------
// LayerNorm over 256: out = LN(a + b) * g + beta. One warp per token.
// ---------------------------------------------------------------------------
__global__ void ln_kernel(const float* __restrict__ a, const float* __restrict__ b,
                          const float* __restrict__ g, const float* __restrict__ beta,
                          float* __restrict__ out)
{
    const int t = blockIdx.x * 4 + (threadIdx.x >> 5);
    const int lane = threadIdx.x & 31;
    const float* pa = a + (size_t)t * DIM;
    const float* pb = b + (size_t)t * DIM;

    float v[8];
    float s = 0.f;
#pragma unroll
    for (int i = 0; i < 8; i++) {
        int c = lane + i * 32;
        v[i] = pa[c] + pb[c];
        s += v[i];
    }
#pragma unroll
    for (int o = 16; o; o >>= 1) s += __shfl_xor_sync(0xffffffffu, s, o);
    const float mean = s * (1.f / 256.f);
    float var = 0.f;
#pragma unroll
    for (int i = 0; i < 8; i++) { float dd = v[i] - mean; var += dd * dd; }
#pragma unroll
    for (int o = 16; o; o >>= 1) var += __shfl_xor_sync(0xffffffffu, var, o);
    const float rstd = rsqrtf(var * (1.f / 256.f) + 1e-5f);
#pragma unroll
    for (int i = 0; i < 8; i++) {
        int c = lane + i * 32;
        out[(size_t)t * DIM + c] = (v[i] - mean) * rstd * g[c] + beta[c];
    }
}

// ---------------------------------------------------------------------------
extern "C" void kernel_launch(void* const* d_in, const int* in_sizes, int n_in,
                              void* d_out, int out_size)
{
    const float* src  = (const float*)d_in[0];
    const float* pos  = (const float*)d_in[1];
    const float* refp = (const float*)d_in[2];
    const float* Wv   = (const float*)d_in[4];
    const float* bv   = (const float*)d_in[5];
    const float* Wo   = (const float*)d_in[6];
    const float* bo   = (const float*)d_in[7];
    const float* Wa   = (const float*)d_in[8];
    const float* ba   = (const float*)d_in[9];
    const float* Wout = (const float*)d_in[10];
    const float* bout = (const float*)d_in[11];
    const float* g1   = (const float*)d_in[12];
    const float* be1  = (const float*)d_in[13];
    const float* W1   = (const float*)d_in[14];
    const float* b1   = (const float*)d_in[15];
    const float* W2   = (const float*)d_in[16];
    const float* b2   = (const float*)d_in[17];
    const float* g2   = (const float*)d_in[18];
    const float* be2  = (const float*)d_in[19];
    float* out = (float*)d_out;

    __nv_bfloat16* pvb;
    float *poa, *psamp, *psrc2, *px, *phid, *pffn, *pqr;
    float *wtv, *wtoa, *wtout, *wt1, *wt2, *pboa;
    cudaGetSymbolAddress((void**)&pvb,   g_valbf);
    cudaGetSymbolAddress((void**)&poa,   g_offattn);
    cudaGetSymbolAddress((void**)&psamp, g_samp);
    cudaGetSymbolAddress((void**)&psrc2, g_src2);
    cudaGetSymbolAddress((void**)&px,    g_x);
    cudaGetSymbolAddress((void**)&phid,  g_hid);
    cudaGetSymbolAddress((void**)&pffn,  g_ffn);
    cudaGetSymbolAddress((void**)&pqr,   g_qr);
    cudaGetSymbolAddress((void**)&wtv,   g_wtv);
    cudaGetSymbolAddress((void**)&wtoa,  g_wtoa);
    cudaGetSymbolAddress((void**)&wtout, g_wtout);
    cudaGetSymbolAddress((void**)&wt1,   g_wt1);
    cudaGetSymbolAddress((void**)&wt2,   g_wt2);
    cudaGetSymbolAddress((void**)&pboa,  g_boa);

    const int DSM = 98304;  // 3 stages x 32KB
    cudaFuncSetAttribute(mma_gemm<0,0,1,1>, cudaFuncAttributeMaxDynamicSharedMemorySize, DSM);
    cudaFuncSetAttribute(mma_gemm<0,0,0,0>, cudaFuncAttributeMaxDynamicSharedMemorySize, DSM);
    cudaFuncSetAttribute(mma_gemm<1,1,1,0>, cudaFuncAttributeMaxDynamicSharedMemorySize, DSM);

    // Weight prep (tiny) + q pre-round
    transpose_tf32<<<(256*256 + 255) / 256, 256>>>(Wv,   wtv,  256, 256);
    transpose_tf32<<<(256*256 + 255) / 256, 256>>>(Wo,   wtoa, 256, 256);
    transpose_tf32<<<(256*128 + 255) / 256, 256>>>(Wa,   wtoa + 256*256, 256, 128);
    transpose_tf32<<<(256*256 + 255) / 256, 256>>>(Wout, wtout, 256, 256);
    transpose_tf32<<<(256*1024 + 255) / 256, 256>>>(W1,  wt1,  256, 1024);
    transpose_tf32<<<(1024*256 + 255) / 256, 256>>>(W2,  wt2, 1024, 256);
    concat_bias<<<1, 384>>>(bo, ba, pboa);
    preround_q<<<(TTOK*DIM/4) / 256, 256>>>((const float4*)src, (const float4*)pos, (uint4*)pqr);

    const int MT = TTOK / 128;  // 340 M-tiles

    // value (bf16 out) = src @ Wv + bv   (A rounded in-register)
    mma_gemm<0,0,1,1><<<MT * 2, 256, DSM>>>(src, wtv, bv, nullptr, pvb, 256, 256, MT);
    // offsets|logits = q @ [Woff|Wattn] + [boff|battn]
    mma_gemm<0,0,0,0><<<MT * 3, 256, DSM>>>(pqr, wtoa, pboa, poa, nullptr, 256, 384, MT);
    // deformable sampling (softmax fused; writes tf32-rounded samp)
    sample_kernel<<<TTOK / 8, 256>>>(pvb, poa, refp, psamp);
    // src2 = samp @ Wout + bout
    mma_gemm<0,0,0,0><<<MT * 2, 256, DSM>>>(psamp, wtout, bout, psrc2, nullptr, 256, 256, MT);
    // x = LN1(src + src2)
    ln_kernel<<<TTOK / 4, 128>>>(src, psrc2, g1, be1, px);
    // hid = relu(x @ W1 + b1)  (A rounded in-register; output tf32-rounded)
    mma_gemm<1,1,1,0><<<MT * 8, 256, DSM>>>(px, wt1, b1, phid, nullptr, 256, 1024, MT);
    // ffn = hid @ W2 + b2
    mma_gemm<0,0,0,0><<<MT * 2, 256, DSM>>>(phid, wt2, b2, pffn, nullptr, 1024, 256, MT);
    // out = LN2(x + ffn)
    ln_kernel<<<TTOK / 4, 128>>>(px, pffn, g2, be2, out);
}

// round 6
// speedup vs baseline: 5.1310x; 1.6152x over previous
#include <cuda_runtime.h>
#include <cuda_bf16.h>
#include <cstdint>
#include <math.h>

// Problem constants (static per reference)
#define NBATCH 8
#define LQ     5440
#define TTOK   (NBATCH*LQ)      // 43520
#define DIM    256
#define NHEAD  8
#define HD     32
#define NLVL   4
#define NPT    4
#define DFF    1024

// Scratch (device globals; no runtime allocation)
__device__ __nv_bfloat16 g_srcb [(size_t)TTOK*DIM];
__device__ __nv_bfloat16 g_qb   [(size_t)TTOK*DIM];
__device__ __nv_bfloat16 g_valbf[(size_t)TTOK*DIM];
__device__ float         g_offattn[(size_t)TTOK*384];
__device__ __nv_bfloat16 g_sampb[(size_t)TTOK*DIM];
__device__ float         g_src2 [(size_t)TTOK*DIM];
__device__ float         g_x    [(size_t)TTOK*DIM];
__device__ __nv_bfloat16 g_xb   [(size_t)TTOK*DIM];
__device__ __nv_bfloat16 g_hidb [(size_t)TTOK*DFF];
__device__ float         g_ffn  [(size_t)TTOK*DIM];
// Transposed ([N][K]) bf16 weights
__device__ __nv_bfloat16 g_wtv  [256*256];
__device__ __nv_bfloat16 g_wtoa [384*256];
__device__ __nv_bfloat16 g_wtout[256*256];
__device__ __nv_bfloat16 g_wt1  [1024*256];
__device__ __nv_bfloat16 g_wt2  [256*1024];
__device__ float         g_boa  [384];

// ---------------------------------------------------------------------------
// Helpers
// ---------------------------------------------------------------------------
__device__ __forceinline__ uint32_t smem_u32(const void* p) {
    uint32_t a;
    asm("{ .reg .u64 t; cvta.to.shared.u64 t, %1; cvt.u32.u64 %0, t; }" : "=r"(a) : "l"(p));
    return a;
}
__device__ __forceinline__ void cpasync16(uint32_t dst, const void* src) {
    asm volatile("cp.async.cg.shared.global [%0], [%1], 16;" :: "r"(dst), "l"(src));
}
#define CP_COMMIT() asm volatile("cp.async.commit_group;" ::: "memory")
#define CP_WAIT1()  asm volatile("cp.async.wait_group 1;" ::: "memory")

__device__ __forceinline__ void ldmx4(uint32_t& f0, uint32_t& f1, uint32_t& f2, uint32_t& f3,
                                      uint32_t addr) {
    asm volatile("ldmatrix.sync.aligned.m8n8.x4.shared.b16 {%0,%1,%2,%3}, [%4];"
                 : "=r"(f0), "=r"(f1), "=r"(f2), "=r"(f3) : "r"(addr));
}
__device__ __forceinline__ void mma_bf16(float* c, uint32_t a0, uint32_t a1,
                                         uint32_t a2, uint32_t a3,
                                         uint32_t b0, uint32_t b1) {
    asm volatile(
        "mma.sync.aligned.m16n8k16.row.col.f32.bf16.bf16.f32 "
        "{%0,%1,%2,%3}, {%4,%5,%6,%7}, {%8,%9}, {%0,%1,%2,%3};"
        : "+f"(c[0]), "+f"(c[1]), "+f"(c[2]), "+f"(c[3])
        : "r"(a0), "r"(a1), "r"(a2), "r"(a3), "r"(b0), "r"(b1));
}

// ---------------------------------------------------------------------------
// One-shot prep: all weight transposes (fp32 [K][N] -> bf16 [N][K]),
// bias concat, and src/q bf16 conversion. Single launch.
// Blocks [0,2944): weights; [2944, 2944+10880): activations; last: bias.
// ---------------------------------------------------------------------------
#define PREP_WBLK 2944
#define PREP_ABLK 10880
__global__ void prep_kernel(const float* __restrict__ Wv, const float* __restrict__ Wo,
                            const float* __restrict__ Wa, const float* __restrict__ Wout,
                            const float* __restrict__ W1, const float* __restrict__ W2,
                            const float* __restrict__ bo, const float* __restrict__ ba,
                            const float4* __restrict__ src, const float4* __restrict__ pos,
                            __nv_bfloat16* __restrict__ wtv, __nv_bfloat16* __restrict__ wtoa,
                            __nv_bfloat16* __restrict__ wtout, __nv_bfloat16* __restrict__ wt1,
                            __nv_bfloat16* __restrict__ wt2, float* __restrict__ boa,
                            __nv_bfloat16* __restrict__ srcb, __nv_bfloat16* __restrict__ qb)
{
    int b = blockIdx.x;
    if (b < PREP_WBLK) {
        int idx = b * 256 + threadIdx.x;  // 0..753663
        float v; __nv_bfloat16* dst;
        if (idx < 65536) {                       // Wv [256,256]
            int n = idx >> 8, k = idx & 255; v = Wv[k * 256 + n]; dst = wtv + idx;
        } else if (idx < 163840) {               // Woa [384,256] = [Wo|Wa]
            int j = idx - 65536; int n = j >> 8, k = j & 255;
            v = (n < 256) ? Wo[k * 256 + n] : Wa[k * 128 + (n - 256)]; dst = wtoa + j;
        } else if (idx < 229376) {               // Wout [256,256]
            int j = idx - 163840; int n = j >> 8, k = j & 255; v = Wout[k * 256 + n]; dst = wtout + j;
        } else if (idx < 491520) {               // W1 [1024,256]
            int j = idx - 229376; int n = j >> 8, k = j & 255; v = W1[k * 1024 + n]; dst = wt1 + j;
        } else {                                 // W2 [256,1024]
            int j = idx - 491520; int n = j >> 10, k = j & 1023; v = W2[k * 256 + n]; dst = wt2 + j;
        }
        *dst = __float2bfloat16(v);
    } else if (b < PREP_WBLK + PREP_ABLK) {
        int idx = (b - PREP_WBLK) * 256 + threadIdx.x;   // float4 index
        float4 s = src[idx], p = pos[idx];
        __nv_bfloat162 s01 = __float22bfloat162_rn(make_float2(s.x, s.y));
        __nv_bfloat162 s23 = __float22bfloat162_rn(make_float2(s.z, s.w));
        __nv_bfloat162 q01 = __float22bfloat162_rn(make_float2(s.x + p.x, s.y + p.y));
        __nv_bfloat162 q23 = __float22bfloat162_rn(make_float2(s.z + p.z, s.w + p.w));
        ((uint2*)srcb)[idx] = make_uint2(*(uint32_t*)&s01, *(uint32_t*)&s23);
        ((uint2*)qb)[idx]   = make_uint2(*(uint32_t*)&q01, *(uint32_t*)&q23);
    } else {
        int i = threadIdx.x;
        if (i < 384) boa[i] = (i < 256) ? bo[i] : ba[i - 256];
    }
}

// ---------------------------------------------------------------------------
// bf16 tensor GEMM, cp.async 3-stage pipeline + ldmatrix fragments.
// C[M x Nc] = act( A @ Wt^T + bias ). A bf16 [M,K] row-major; Wt bf16 [Nc,K].
// CTA 128x128, 8 warps (2m x 4n), warp 64x32, BK=64 (128B rows, SW128 XOR).
// OBF: bf16 output to C16; else fp32 to C.
// ---------------------------------------------------------------------------
#define BK 64
template<int ACT, int OBF>
__global__ void __launch_bounds__(256, 2)
mma_gemm(const __nv_bfloat16* __restrict__ A, const __nv_bfloat16* __restrict__ Wt,
         const float* __restrict__ bias, float* __restrict__ C,
         __nv_bfloat16* __restrict__ C16, int K, int Nc, int mtiles)
{
    extern __shared__ char smem[];
    // A stages: [st*16384), B stages: 49152 + st*16384  (bytes)
    const uint32_t sbase = smem_u32(smem);

    const int tid = threadIdx.x;
    const int wid = tid >> 5, lane = tid & 31;
    const int g = lane >> 2, tg = lane & 3;
    const int wm = wid & 1, wn = wid >> 1;
    const int mt = blockIdx.x % mtiles;
    const int nt = blockIdx.x / mtiles;
    const int row0 = mt * 128, col0 = nt * 128;

    // ldmatrix lane roles
    const int a_r  = (lane & 7) + ((lane >> 3) & 1) * 8;  // row within m16
    const int a_kh = (lane >> 4) & 1;                     // k-half (8 elems)
    const int b_r  = (lane & 7) + ((lane >> 4) << 3);     // row within n16
    const int b_kh = (lane >> 3) & 1;

    float acc[4][4][4];
#pragma unroll
    for (int i = 0; i < 4; i++)
#pragma unroll
        for (int j = 0; j < 4; j++)
#pragma unroll
            for (int k = 0; k < 4; k++) acc[i][j][k] = 0.f;

    auto load_chunk = [&](int k0, int st) {
#pragma unroll
        for (int i = 0; i < 4; i++) {
            int idx = tid + i * 256;
            int r = idx >> 3, gc = idx & 7;
            uint32_t so = (uint32_t)(r * 128 + ((gc ^ (r & 7)) << 4));
            cpasync16(sbase + st * 16384 + so, A + (size_t)(row0 + r) * K + k0 + gc * 8);
            cpasync16(sbase + 49152 + st * 16384 + so, Wt + (size_t)(col0 + r) * K + k0 + gc * 8);
        }
    };

    const int nchunk = K / BK;
    load_chunk(0, 0);
    CP_COMMIT();
    if (nchunk > 1) load_chunk(BK, 1);
    CP_COMMIT();

    for (int ch = 0; ch < nchunk; ch++) {
        CP_WAIT1();
        __syncthreads();
        if (ch + 2 < nchunk) load_chunk((ch + 2) * BK, (ch + 2) % 3);
        CP_COMMIT();

        const uint32_t Ab = sbase + (ch % 3) * 16384;
        const uint32_t Bb = sbase + 49152 + (ch % 3) * 16384;
#pragma unroll
        for (int ks = 0; ks < 4; ks++) {
            uint32_t bf[4][2];
#pragma unroll
            for (int np = 0; np < 2; np++) {
                int r = wn * 32 + np * 16 + b_r;
                uint32_t addr = Bb + r * 128 + (((ks * 2 + b_kh) ^ (r & 7)) << 4);
                ldmx4(bf[np * 2][0], bf[np * 2][1], bf[np * 2 + 1][0], bf[np * 2 + 1][1], addr);
            }
#pragma unroll
            for (int mf = 0; mf < 4; mf++) {
                int r = wm * 64 + mf * 16 + a_r;
                uint32_t addr = Ab + r * 128 + (((ks * 2 + a_kh) ^ (r & 7)) << 4);
                uint32_t a0, a1, a2, a3;
                ldmx4(a0, a1, a2, a3, addr);
#pragma unroll
                for (int nf = 0; nf < 4; nf++)
                    mma_bf16(acc[mf][nf], a0, a1, a2, a3, bf[nf][0], bf[nf][1]);
            }
        }
    }

    // Epilogue
#pragma unroll
    for (int mf = 0; mf < 4; mf++) {
#pragma unroll
        for (int nf = 0; nf < 4; nf++) {
            int row = row0 + wm * 64 + mf * 16 + g;
            int col = col0 + wn * 32 + nf * 8 + tg * 2;
            float b0 = bias[col], b1 = bias[col + 1];
            float o[4];
            o[0] = acc[mf][nf][0] + b0; o[1] = acc[mf][nf][1] + b1;
            o[2] = acc[mf][nf][2] + b0; o[3] = acc[mf][nf][3] + b1;
            if (ACT) {
#pragma unroll
                for (int i = 0; i < 4; i++) o[i] = fmaxf(o[i], 0.f);
            }
            if (OBF) {
                *(__nv_bfloat162*)(&C16[(size_t)row * Nc + col]) =
                    __float22bfloat162_rn(make_float2(o[0], o[1]));
                *(__nv_bfloat162*)(&C16[(size_t)(row + 8) * Nc + col]) =
                    __float22bfloat162_rn(make_float2(o[2], o[3]));
            } else {
                *(float2*)(&C[(size_t)row * Nc + col]) = make_float2(o[0], o[1]);
                *(float2*)(&C[(size_t)(row + 8) * Nc + col]) = make_float2(o[2], o[3]);
            }
        }
    }
}

// ---------------------------------------------------------------------------
// Deformable sampling with fused softmax. Warp per token: 8 heads x 4 lanes,
// 8 dims (one uint4 of bf16) per lane. Value bf16; samp output bf16.
// ---------------------------------------------------------------------------
__global__ void __launch_bounds__(256)
sample_kernel(const __nv_bfloat16* __restrict__ valbf,
              const float* __restrict__ offattn,
              const float* __restrict__ ref,
              __nv_bfloat16* __restrict__ sampb)
{
    const int t = blockIdx.x * 8 + (threadIdx.x >> 5);
    const int lane = threadIdx.x & 31;
    const int h = lane >> 2;
    const int d8 = lane & 3;
    const int n = t / LQ;

    const float* rowp = offattn + (size_t)t * 384;
    const float* lp = rowp + 256 + h * 16;
    const float* op = rowp + h * 32;

    float lg[16];
    float mx = -1e30f;
#pragma unroll
    for (int j = 0; j < 16; j++) { lg[j] = lp[j]; mx = fmaxf(mx, lg[j]); }
    float ssum = 0.f;
#pragma unroll
    for (int j = 0; j < 16; j++) { lg[j] = expf(lg[j] - mx); ssum += lg[j]; }
    const float inv = 1.f / ssum;

    const int Hs[4] = {64, 32, 16, 8};
    const int St[4] = {0, 4096, 5120, 5376};

    float acc[8];
#pragma unroll
    for (int i = 0; i < 8; i++) acc[i] = 0.f;

#pragma unroll
    for (int l = 0; l < NLVL; l++) {
        const int H = Hs[l];
        const int W = Hs[l];
        const float fH = (float)H, fW = (float)W;
        const float invW = 1.f / fW, invH = 1.f / fH;
        const float refx = ref[((size_t)t * NLVL + l) * 2 + 0];
        const float refy = ref[((size_t)t * NLVL + l) * 2 + 1];
        const uint4* vb = (const uint4*)(valbf + ((size_t)(n * LQ + St[l])) * DIM + h * HD + d8 * 8);
#pragma unroll
        for (int p = 0; p < NPT; p++) {
            float ox = op[(l * NPT + p) * 2 + 0];
            float oy = op[(l * NPT + p) * 2 + 1];
            float xf = (refx + ox * invW) * fW - 0.5f;
            float yf = (refy + oy * invH) * fH - 0.5f;
            float x0f = floorf(xf), y0f = floorf(yf);
            int x0 = (int)x0f, y0 = (int)y0f;
            float wx1 = xf - x0f, wy1 = yf - y0f;
            float wx0 = 1.f - wx1, wy0 = 1.f - wy1;
            float w = lg[l * NPT + p] * inv;

            bool xin0 = (x0 >= 0) & (x0 < W);
            bool xin1 = (x0 + 1 >= 0) & (x0 + 1 < W);
            bool yin0 = (y0 >= 0) & (y0 < H);
            bool yin1 = (y0 + 1 >= 0) & (y0 + 1 < H);

            float cw[4] = { w * wy0 * wx0, w * wy0 * wx1, w * wy1 * wx0, w * wy1 * wx1 };
            bool vld[4] = { yin0 && xin0, yin0 && xin1, yin1 && xin0, yin1 && xin1 };
            int  idx[4] = { y0 * W + x0, y0 * W + x0 + 1, (y0 + 1) * W + x0, (y0 + 1) * W + x0 + 1 };
#pragma unroll
            for (int cnr = 0; cnr < 4; cnr++) {
                uint4 u = make_uint4(0u, 0u, 0u, 0u);
                if (vld[cnr]) u = vb[(size_t)idx[cnr] * (DIM / 8)];
                const __nv_bfloat162* q2 = (const __nv_bfloat162*)&u;
                float c = cw[cnr];
#pragma unroll
                for (int j = 0; j < 4; j++) {
                    float2 f = __bfloat1622float2(q2[j]);
                    acc[2 * j + 0] = fmaf(f.x, c, acc[2 * j + 0]);
                    acc[2 * j + 1] = fmaf(f.y, c, acc[2 * j + 1]);
                }
            }
        }
    }
    __nv_bfloat162 ob[4];
#pragma unroll
    for (int j = 0; j < 4; j++)
        ob[j] = __float22bfloat162_rn(make_float2(acc[2 * j], acc[2 * j + 1]));
    *(uint4*)(sampb + (size_t)t * DIM + h * HD + d8 * 8) = *(uint4*)ob;
}

// ---------------------------------------------------------------------------
// LayerNorm over 256: out = LN(a + b) * g + beta. One warp per token.
// Optional bf16 secondary output.
// ---------------------------------------------------------------------------
__global__ void ln_kernel(const float* __restrict__ a, const float* __restrict__ b,
                          const float* __restrict__ g, const float* __restrict__ beta,
                          float* __restrict__ out, __nv_bfloat16* __restrict__ out_b)
{
    const int t = blockIdx.x * 4 + (threadIdx.x >> 5);
    const int lane = threadIdx.x & 31;
    const float* pa = a + (size_t)t * DIM;
    const float* pb = b + (size_t)t * DIM;

    float v[8];
    float s = 0.f;
#pragma unroll
    for (int i = 0; i < 8; i++) {
        int c = lane + i * 32;
        v[i] = pa[c] + pb[c];
        s += v[i];
    }
#pragma unroll
    for (int o = 16; o; o >>= 1) s += __shfl_xor_sync(0xffffffffu, s, o);
    const float mean = s * (1.f / 256.f);
    float var = 0.f;
#pragma unroll
    for (int i = 0; i < 8; i++) { float dd = v[i] - mean; var += dd * dd; }
#pragma unroll
    for (int o = 16; o; o >>= 1) var += __shfl_xor_sync(0xffffffffu, var, o);
    const float rstd = rsqrtf(var * (1.f / 256.f) + 1e-5f);
#pragma unroll
    for (int i = 0; i < 8; i++) {
        int c = lane + i * 32;
        float y = (v[i] - mean) * rstd * g[c] + beta[c];
        out[(size_t)t * DIM + c] = y;
        if (out_b) out_b[(size_t)t * DIM + c] = __float2bfloat16(y);
    }
}

// ---------------------------------------------------------------------------
extern "C" void kernel_launch(void* const* d_in, const int* in_sizes, int n_in,
                              void* d_out, int out_size)
{
    const float* src  = (const float*)d_in[0];
    const float* pos  = (const float*)d_in[1];
    const float* refp = (const float*)d_in[2];
    const float* Wv   = (const float*)d_in[4];
    const float* bv   = (const float*)d_in[5];
    const float* Wo   = (const float*)d_in[6];
    const float* bo   = (const float*)d_in[7];
    const float* Wa   = (const float*)d_in[8];
    const float* ba   = (const float*)d_in[9];
    const float* Wout = (const float*)d_in[10];
    const float* bout = (const float*)d_in[11];
    const float* g1   = (const float*)d_in[12];
    const float* be1  = (const float*)d_in[13];
    const float* W1   = (const float*)d_in[14];
    const float* b1   = (const float*)d_in[15];
    const float* W2   = (const float*)d_in[16];
    const float* b2   = (const float*)d_in[17];
    const float* g2   = (const float*)d_in[18];
    const float* be2  = (const float*)d_in[19];
    float* out = (float*)d_out;

    __nv_bfloat16 *psrcb, *pqb, *pvb, *psampb, *pxb, *phidb;
    __nv_bfloat16 *wtv, *wtoa, *wtout, *wt1, *wt2;
    float *poa, *psrc2, *px, *pffn, *pboa;
    cudaGetSymbolAddress((void**)&psrcb, g_srcb);
    cudaGetSymbolAddress((void**)&pqb,   g_qb);
    cudaGetSymbolAddress((void**)&pvb,   g_valbf);
    cudaGetSymbolAddress((void**)&poa,   g_offattn);
    cudaGetSymbolAddress((void**)&psampb,g_sampb);
    cudaGetSymbolAddress((void**)&psrc2, g_src2);
    cudaGetSymbolAddress((void**)&px,    g_x);
    cudaGetSymbolAddress((void**)&pxb,   g_xb);
    cudaGetSymbolAddress((void**)&phidb, g_hidb);
    cudaGetSymbolAddress((void**)&pffn,  g_ffn);
    cudaGetSymbolAddress((void**)&wtv,   g_wtv);
    cudaGetSymbolAddress((void**)&wtoa,  g_wtoa);
    cudaGetSymbolAddress((void**)&wtout, g_wtout);
    cudaGetSymbolAddress((void**)&wt1,   g_wt1);
    cudaGetSymbolAddress((void**)&wt2,   g_wt2);
    cudaGetSymbolAddress((void**)&pboa,  g_boa);

    const int DSM = 98304;  // 3 stages x (16KB A + 16KB B)
    cudaFuncSetAttribute(mma_gemm<0,0>, cudaFuncAttributeMaxDynamicSharedMemorySize, DSM);
    cudaFuncSetAttribute(mma_gemm<0,1>, cudaFuncAttributeMaxDynamicSharedMemorySize, DSM);
    cudaFuncSetAttribute(mma_gemm<1,1>, cudaFuncAttributeMaxDynamicSharedMemorySize, DSM);

    // One-shot prep
    prep_kernel<<<PREP_WBLK + PREP_ABLK + 1, 256>>>(
        Wv, Wo, Wa, Wout, W1, W2, bo, ba,
        (const float4*)src, (const float4*)pos,
        wtv, wtoa, wtout, wt1, wt2, pboa, psrcb, pqb);

    const int MT = TTOK / 128;  // 340 M-tiles

    // value (bf16) = src @ Wv + bv
    mma_gemm<0,1><<<MT * 2, 256, DSM>>>(psrcb, wtv, bv, nullptr, pvb, 256, 256, MT);
    // offsets|logits (fp32) = q @ [Woff|Wattn] + [boff|battn]
    mma_gemm<0,0><<<MT * 3, 256, DSM>>>(pqb, wtoa, pboa, poa, nullptr, 256, 384, MT);
    // deformable sampling (softmax fused; bf16 out)
    sample_kernel<<<TTOK / 8, 256>>>(pvb, poa, refp, psampb);
    // src2 (fp32) = samp @ Wout + bout
    mma_gemm<0,0><<<MT * 2, 256, DSM>>>(psampb, wtout, bout, psrc2, nullptr, 256, 256, MT);
    // x = LN1(src + src2)  (fp32 + bf16 copies)
    ln_kernel<<<TTOK / 4, 128>>>(src, psrc2, g1, be1, px, pxb);
    // hid (bf16) = relu(x @ W1 + b1)
    mma_gemm<1,1><<<MT * 8, 256, DSM>>>(pxb, wt1, b1, nullptr, phidb, 256, 1024, MT);
    // ffn (fp32) = hid @ W2 + b2
    mma_gemm<0,0><<<MT * 2, 256, DSM>>>(phidb, wt2, b2, pffn, nullptr, 1024, 256, MT);
    // out = LN2(x + ffn)
    ln_kernel<<<TTOK / 4, 128>>>(px, pffn, g2, be2, out, nullptr);
}